// round 1
// baseline (speedup 1.0000x reference)
#include <cuda_runtime.h>
#include <stdint.h>

#define NIMG 32
#define HW   65536

// ---------------- device scratch (no allocs allowed) ----------------
static __device__ float         g_mn[NIMG];
static __device__ float         g_mx[NIMG];
static __device__ unsigned char g_q[NIMG * HW];     // 2 MB quantized images
static __device__ float         g_feat[NIMG * 6 * 8];

// ---------------- kernel 1: per-image min/max ----------------
__global__ void __launch_bounds__(512) k_minmax(const float* __restrict__ x) {
    int b = blockIdx.x;
    const float4* p = reinterpret_cast<const float4*>(x) + (size_t)b * 16384;
    float mn = 3.4e38f, mx = -3.4e38f;
    for (int i = threadIdx.x; i < 16384; i += 512) {
        float4 v = p[i];
        mn = fminf(mn, fminf(fminf(v.x, v.y), fminf(v.z, v.w)));
        mx = fmaxf(mx, fmaxf(fmaxf(v.x, v.y), fmaxf(v.z, v.w)));
    }
#pragma unroll
    for (int o = 16; o; o >>= 1) {
        mn = fminf(mn, __shfl_xor_sync(0xffffffffu, mn, o));
        mx = fmaxf(mx, __shfl_xor_sync(0xffffffffu, mx, o));
    }
    __shared__ float smn[16], smx[16];
    int w = threadIdx.x >> 5, l = threadIdx.x & 31;
    if (l == 0) { smn[w] = mn; smx[w] = mx; }
    __syncthreads();
    if (w == 0) {
        mn = (l < 16) ? smn[l] : 3.4e38f;
        mx = (l < 16) ? smx[l] : -3.4e38f;
#pragma unroll
        for (int o = 16; o; o >>= 1) {
            mn = fminf(mn, __shfl_xor_sync(0xffffffffu, mn, o));
            mx = fmaxf(mx, __shfl_xor_sync(0xffffffffu, mx, o));
        }
        if (l == 0) { g_mn[b] = mn; g_mx[b] = mx; }
    }
}

// ---------------- kernel 2: quantize to uint8 levels ----------------
__device__ __forceinline__ unsigned char quant1(float v, float mn, float dn) {
    float t = (v - mn) / dn * 255.0f;          // same op order as reference
    int qi = (int)floorf(t);
    qi = min(255, max(0, qi));
    return (unsigned char)qi;
}

__global__ void __launch_bounds__(256) k_quant(const float* __restrict__ x) {
    int b = blockIdx.y;
    int i = blockIdx.x * 256 + threadIdx.x;    // 64*256 = 16384 float4 per image
    float mn = g_mn[b];
    float dn = (g_mx[b] - mn) + 1e-8f;
    float4 v = reinterpret_cast<const float4*>(x)[(size_t)b * 16384 + i];
    uchar4 o;
    o.x = quant1(v.x, mn, dn);
    o.y = quant1(v.y, mn, dn);
    o.z = quant1(v.z, mn, dn);
    o.w = quant1(v.w, mn, dn);
    reinterpret_cast<uchar4*>(g_q)[(size_t)b * 16384 + i] = o;
}

// ---------------- kernel 3: GLCM histogram + features ----------------
// Packed uint16 bins in 128 KB dynamic smem. Swizzled word index so the
// transpose read in the feature sweep is bank-conflict-free.
__device__ __forceinline__ int hword(int i, int j) {
    return i * 128 + ((j >> 1) ^ (i & 31));
}

template <int DR, int DC>
__device__ void glcm_one(int b, int offidx, uint32_t* h) {
    constexpr int adr = DR < 0 ? -DR : DR;
    constexpr int adc = DC < 0 ? -DC : DC;
    constexpr int r0  = DR < 0 ? -DR : 0;
    constexpr int c0  = DC < 0 ? -DC : 0;
    constexpr int rh  = 256 - adr;
    constexpr int cw  = 256 - adc;
    constexpr int np  = rh * cw;               // <= 65280 < 2^16  -> u16 safe
    const float S    = 2.0f * (float)np;
    const float invS = 1.0f / S;

    const unsigned char* __restrict__ q = g_q + (size_t)b * HW;
    int tid = threadIdx.x;

    for (int w = tid; w < 32768; w += 1024) h[w] = 0u;
    __syncthreads();

    // build histogram
    for (int p = tid; p < np; p += 1024) {
        int r = p / cw;                        // cw is constexpr -> magic div
        int c = p - r * cw;
        int a  = q[(r0 + r) * 256 + (c0 + c)];
        int bb = q[(r0 + r + DR) * 256 + (c0 + c + DC)];
        atomicAdd(&h[hword(a, bb)], 1u << ((bb & 1) * 16));
    }
    __syncthreads();

    // sweep upper triangle (i <= j); g = c[i][j] + c[j][i] (diag: 2*c[i][i])
    float s_con = 0.f, s_dis = 0.f, s_hom = 0.f, s_asm = 0.f;
    float s_r = 0.f, s_r2 = 0.f, s_rc = 0.f, s_ent = 0.f, s_nz = 0.f;

    for (int idx = tid; idx < 65536; idx += 1024) {
        int i = idx >> 8, j = idx & 255;
        if (j < i) continue;
        uint32_t g1 = (h[hword(i, j)] >> ((j & 1) * 16)) & 0xFFFFu;
        uint32_t g;
        float w;
        if (i == j) { g = g1 + g1; w = 1.0f; }
        else {
            uint32_t g2 = (h[hword(j, i)] >> ((i & 1) * 16)) & 0xFFFFu;
            g = g1 + g2; w = 2.0f;
        }
        if (g == 0u) continue;                 // zero bins handled in closed form
        float gf = (float)g;
        float gw = gf * w;
        float d  = (float)(i - j);
        float d2 = d * d;
        s_con += gw * d2;
        s_dis += gw * fabsf(d);
        s_hom += __fdividef(gw, 1.0f + d2);
        s_asm += gf * gf * w;
        float ip = (float)i - 127.5f, jp = (float)j - 127.5f;
        float hw_ = 0.5f * w;
        s_r  += gf * (ip + jp) * hw_;
        s_r2 += gf * (ip * ip + jp * jp) * hw_;
        s_rc += gf * (ip * jp) * w;
        float Pe = gf * invS + 1e-8f;
        s_ent += w * Pe * __log2f(Pe);
        s_nz  += w;
    }

    // block reduction: 9 accumulators, 32 warps
    __shared__ float red[9][33];
    float vals[9] = {s_con, s_dis, s_hom, s_asm, s_r, s_r2, s_rc, s_ent, s_nz};
    int lane = tid & 31, wid = tid >> 5;
#pragma unroll
    for (int k = 0; k < 9; k++)
#pragma unroll
        for (int o = 16; o; o >>= 1)
            vals[k] += __shfl_xor_sync(0xffffffffu, vals[k], o);
    if (lane == 0)
#pragma unroll
        for (int k = 0; k < 9; k++) red[k][wid] = vals[k];
    __syncthreads();
    if (wid == 0) {
#pragma unroll
        for (int k = 0; k < 9; k++) {
            float v = red[k][lane];
#pragma unroll
            for (int o = 16; o; o >>= 1)
                v += __shfl_xor_sync(0xffffffffu, v, o);
            vals[k] = v;
        }
        if (lane == 0) {
            float contrast = vals[0] * invS;
            float dissim   = vals[1] * invS;
            float homog    = vals[2] * invS;
            float asmv     = vals[3] * invS * invS;
            float energy   = sqrtf(asmv);
            float mu  = vals[4] * invS;                     // centered mean
            float var = vals[5] * invS - mu * mu;
            if (var < 0.f) var = 0.f;
            float cov = vals[6] * invS - mu * mu;
            float denom = var;                              // std_i*std_j (P symmetric)
            float corr  = (denom < 1e-15f) ? 1.0f : cov / fmaxf(denom, 1e-15f);
            // zero bins: Pe = eps -> eps*log2(eps) each
            const float zterm = 1e-8f * (-26.5754247591f);  // 1e-8 * log2(1e-8)
            float entropy = -(vals[7] + (65536.0f - vals[8]) * zterm);
            float* f = g_feat + ((size_t)b * 6 + offidx) * 8;
            f[0] = contrast; f[1] = dissim; f[2] = homog; f[3] = energy;
            f[4] = corr;     f[5] = asmv;   f[6] = entropy; f[7] = var;
        }
    }
}

__global__ void __launch_bounds__(1024) k_glcm() {
    extern __shared__ uint32_t h[];
    int off = blockIdx.x;   // 0..5
    int b   = blockIdx.y;   // 0..31
    switch (off) {
        case 0: glcm_one< 0,  1>(b, 0, h); break;
        case 1: glcm_one< 0,  2>(b, 1, h); break;
        case 2: glcm_one< 1,  0>(b, 2, h); break;
        case 3: glcm_one< 2, -1>(b, 3, h); break;
        case 4: glcm_one<-1,  1>(b, 4, h); break;
        case 5: glcm_one<-2,  1>(b, 5, h); break;
    }
}

// ---------------- kernel 4: broadcast features to output ----------------
__global__ void __launch_bounds__(256) k_bcast(float* __restrict__ out) {
    int blk = blockIdx.x;               // 0..2047 = (b, ch) planes
    int b = blk >> 6, ch = blk & 63;
    int off = ch >> 3;
    if (off >= 6) off -= 6;             // channels 48..63 duplicate offsets 0,1
    float v = g_feat[((size_t)b * 6 + off) * 8 + (ch & 7)];
    float4 vv = make_float4(v, v, v, v);
    float4* p = reinterpret_cast<float4*>(out) + (size_t)blk * 16384;
    for (int i = threadIdx.x; i < 16384; i += 256) p[i] = vv;
}

// ---------------- launch ----------------
extern "C" void kernel_launch(void* const* d_in, const int* in_sizes, int n_in,
                              void* d_out, int out_size) {
    const float* x = (const float*)d_in[0];
    float* out = (float*)d_out;

    cudaFuncSetAttribute(k_glcm, cudaFuncAttributeMaxDynamicSharedMemorySize, 131072);

    k_minmax<<<NIMG, 512>>>(x);
    k_quant<<<dim3(64, NIMG), 256>>>(x);
    k_glcm<<<dim3(6, NIMG), 1024, 131072>>>();
    k_bcast<<<NIMG * 64, 256>>>(out);
}